// round 12
// baseline (speedup 1.0000x reference)
#include <cuda_runtime.h>
#include <cstdint>

#define BATCH     512
#define IMGS      128
#define GRID0     16
#define NP        256        // 16*16 patches
#define PK        64         // patch pixels (8x8)
#define BOND      128
#define RANK      64
#define EMB       512

// ---------------- scratch (static device globals: allocation-free) ----------
__device__ float g_h0[BATCH * NP * BOND];   // 67 MB
__device__ float g_h1[BATCH * 64 * BOND];
__device__ float g_h2[BATCH * 16 * BOND];
__device__ float g_h3[BATCH * 4  * BOND];
__device__ float g_h4[BATCH * 1  * BOND];

// ============================================================================
// K1: patchify + patch GEMM + bias + pos
//   rows = b*256 + p (131072), cols = 128, K = 64
//   block: 128 rows x 128 cols, 256 threads, 8x8 register tile
// ============================================================================
__global__ void __launch_bounds__(256)
patch_embed_kernel(const float* __restrict__ x,
                   const float* __restrict__ Wp,
                   const float* __restrict__ bp,
                   const float* __restrict__ pos)
{
    extern __shared__ float sm[];
    float* As = sm;                 // [128][65]  (pad -> conflict-free scalar reads)
    float* Ws = sm + 128 * 65;      // [64][128]

    const int tid = threadIdx.x;
    const int r0  = blockIdx.x * 128;

    // load A tile (patchify gather)
    for (int idx = tid; idx < 128 * 64; idx += 256) {
        int i = idx >> 6;           // row within block
        int k = idx & 63;           // pixel within patch
        int row = r0 + i;
        int b = row >> 8, p = row & 255;
        int gy = p >> 4, gx = p & 15;
        int py = k >> 3, px = k & 7;
        As[i * 65 + k] = x[(b * 128 + gy * 8 + py) * 128 + gx * 8 + px];
    }
    // load W (64x128)
    for (int idx = tid; idx < 64 * 128; idx += 256)
        Ws[idx] = Wp[idx];
    __syncthreads();

    const int rg = tid >> 4;        // 16 row groups of 8
    const int cg = tid & 15;        // 16 col groups of 8

    float acc[8][8];
#pragma unroll
    for (int j = 0; j < 8; j++)
#pragma unroll
        for (int i = 0; i < 8; i++) acc[j][i] = 0.f;

#pragma unroll 8
    for (int k = 0; k < 64; k++) {
        float4 w0 = *(const float4*)(Ws + k * 128 + cg * 8);
        float4 w1 = *(const float4*)(Ws + k * 128 + cg * 8 + 4);
        float a[8];
#pragma unroll
        for (int j = 0; j < 8; j++) a[j] = As[(rg * 8 + j) * 65 + k];
#pragma unroll
        for (int j = 0; j < 8; j++) {
            acc[j][0] += a[j] * w0.x; acc[j][1] += a[j] * w0.y;
            acc[j][2] += a[j] * w0.z; acc[j][3] += a[j] * w0.w;
            acc[j][4] += a[j] * w1.x; acc[j][5] += a[j] * w1.y;
            acc[j][6] += a[j] * w1.z; acc[j][7] += a[j] * w1.w;
        }
    }

    float4 bp0 = *(const float4*)(bp + cg * 8);
    float4 bp1 = *(const float4*)(bp + cg * 8 + 4);
#pragma unroll
    for (int j = 0; j < 8; j++) {
        int row = r0 + rg * 8 + j;
        int p = row & 255;
        float4 p0 = *(const float4*)(pos + p * 128 + cg * 8);
        float4 p1 = *(const float4*)(pos + p * 128 + cg * 8 + 4);
        float4 o0, o1;
        o0.x = acc[j][0] + bp0.x + p0.x; o0.y = acc[j][1] + bp0.y + p0.y;
        o0.z = acc[j][2] + bp0.z + p0.z; o0.w = acc[j][3] + bp0.w + p0.w;
        o1.x = acc[j][4] + bp1.x + p1.x; o1.y = acc[j][5] + bp1.y + p1.y;
        o1.z = acc[j][6] + bp1.z + p1.z; o1.w = acc[j][7] + bp1.w + p1.w;
        *(float4*)(g_h0 + (size_t)row * 128 + cg * 8)     = o0;
        *(float4*)(g_h0 + (size_t)row * 128 + cg * 8 + 4) = o1;
    }
}

// ============================================================================
// K2: one CP-tree level.
//   grid: (BATCH/TB, out_nodes). block: 256 threads.
//   per quad: U[b,r] = X[b,:] @ F[:,r]; P[b,r] = prod_q U; out = P @ O
// ============================================================================
template <int TB>
__global__ void __launch_bounds__(256)
cp_level_kernel(const float* __restrict__ in,
                float* __restrict__ out,
                const float* __restrict__ f,
                const float* __restrict__ o,
                int g)   // input grid size
{
    constexpr int BSUB  = TB / 32;   // rows/thread in phase 1
    constexpr int B2SUB = TB / 16;   // rows/thread in phase 2

    extern __shared__ float sm[];
    float* Xs = sm;                  // [TB][129]
    float* Fs = sm + TB * 129;       // [128][64]
    float* Ps = sm;                  // alias over Xs: [TB][65]
    float* Os = Fs;                  // alias over Fs: [64][128]

    const int tid  = threadIdx.x;
    const int node = blockIdx.y;
    const int b0   = blockIdx.x * TB;
    const int g2   = g >> 1;
    const int ny   = node / g2, nx = node % g2;
    const size_t inStride  = (size_t)g * g * BOND;
    const size_t outStride = (size_t)g2 * g2 * BOND;

    const int bg = tid >> 3;         // 32 groups
    const int rg = tid & 7;          // 8 groups of 8 r's

    float p[BSUB][8];
#pragma unroll
    for (int j = 0; j < BSUB; j++)
#pragma unroll
        for (int i = 0; i < 8; i++) p[j][i] = 1.f;

    for (int q = 0; q < 4; q++) {
        int child = (2 * ny + (q >> 1)) * g + 2 * nx + (q & 1);
        const float* xin = in + (size_t)child * BOND;
        const float* fq  = f + (size_t)(node * 4 + q) * BOND * RANK;

        __syncthreads();   // previous compute done before overwriting tiles
        for (int idx = tid; idx < TB * 128; idx += 256) {
            int bb = idx >> 7, c = idx & 127;
            Xs[bb * 129 + c] = xin[(size_t)(b0 + bb) * inStride + c];
        }
        for (int idx = tid; idx < 128 * 64; idx += 256)
            Fs[idx] = fq[idx];
        __syncthreads();

        float u[BSUB][8];
#pragma unroll
        for (int j = 0; j < BSUB; j++)
#pragma unroll
            for (int i = 0; i < 8; i++) u[j][i] = 0.f;

#pragma unroll 8
        for (int k = 0; k < 128; k++) {
            float4 f0v = *(const float4*)(Fs + k * 64 + rg * 8);
            float4 f1v = *(const float4*)(Fs + k * 64 + rg * 8 + 4);
#pragma unroll
            for (int j = 0; j < BSUB; j++) {
                float a = Xs[(bg * BSUB + j) * 129 + k];
                u[j][0] += a * f0v.x; u[j][1] += a * f0v.y;
                u[j][2] += a * f0v.z; u[j][3] += a * f0v.w;
                u[j][4] += a * f1v.x; u[j][5] += a * f1v.y;
                u[j][6] += a * f1v.z; u[j][7] += a * f1v.w;
            }
        }
#pragma unroll
        for (int j = 0; j < BSUB; j++)
#pragma unroll
            for (int i = 0; i < 8; i++) p[j][i] *= u[j][i];
    }

    __syncthreads();    // all reads of Xs/Fs finished
    // stage P (alias of Xs) and O (alias of Fs)
#pragma unroll
    for (int j = 0; j < BSUB; j++)
#pragma unroll
        for (int i = 0; i < 8; i++)
            Ps[(bg * BSUB + j) * 65 + rg * 8 + i] = p[j][i];

    const float* ob = o + (size_t)node * RANK * BOND;
    for (int idx = tid; idx < 64 * 128; idx += 256)
        Os[idx] = ob[idx];
    __syncthreads();

    const int bg2 = tid >> 4;        // 16 groups
    const int cg  = tid & 15;        // 16 groups of 8 c's

    float acc[B2SUB][8];
#pragma unroll
    for (int j = 0; j < B2SUB; j++)
#pragma unroll
        for (int i = 0; i < 8; i++) acc[j][i] = 0.f;

#pragma unroll 8
    for (int r = 0; r < 64; r++) {
        float4 w0 = *(const float4*)(Os + r * 128 + cg * 8);
        float4 w1 = *(const float4*)(Os + r * 128 + cg * 8 + 4);
#pragma unroll
        for (int j = 0; j < B2SUB; j++) {
            float a = Ps[(bg2 * B2SUB + j) * 65 + r];
            acc[j][0] += a * w0.x; acc[j][1] += a * w0.y;
            acc[j][2] += a * w0.z; acc[j][3] += a * w0.w;
            acc[j][4] += a * w1.x; acc[j][5] += a * w1.y;
            acc[j][6] += a * w1.z; acc[j][7] += a * w1.w;
        }
    }

#pragma unroll
    for (int j = 0; j < B2SUB; j++) {
        int b = b0 + bg2 * B2SUB + j;
        float* op = out + (size_t)b * outStride + (size_t)node * BOND + cg * 8;
        float4 s0, s1;
        s0.x = acc[j][0]; s0.y = acc[j][1]; s0.z = acc[j][2]; s0.w = acc[j][3];
        s1.x = acc[j][4]; s1.y = acc[j][5]; s1.z = acc[j][6]; s1.w = acc[j][7];
        *(float4*)(op)     = s0;
        *(float4*)(op + 4) = s1;
    }
}

// ============================================================================
// K3: LayerNorm + head GEMM + row L2-normalize.
//   block: 8 batch rows, 512 threads (one thread per embed column).
// ============================================================================
__global__ void __launch_bounds__(512)
head_kernel(const float* __restrict__ gamma,
            const float* __restrict__ beta,
            const float* __restrict__ Wh,
            const float* __restrict__ bh,
            float* __restrict__ outg)
{
    constexpr int BB = 8;
    __shared__ float hs[BB][BOND];       // 4 KB
    __shared__ float outs[BB][EMB];      // 16 KB
    __shared__ float mu_s[BB], rs_s[BB], rn_s[BB];

    const int tid = threadIdx.x;         // 512
    const int b0  = blockIdx.x * BB;
    const int w   = tid >> 5, lane = tid & 31;

    for (int idx = tid; idx < BB * BOND; idx += 512)
        hs[idx >> 7][idx & 127] = g_h4[(size_t)(b0 + (idx >> 7)) * BOND + (idx & 127)];
    __syncthreads();

    if (w < BB) {
        float s = 0.f, ss = 0.f;
        for (int c = lane; c < BOND; c += 32) {
            float v = hs[w][c]; s += v; ss += v * v;
        }
#pragma unroll
        for (int off = 16; off; off >>= 1) {
            s  += __shfl_xor_sync(0xffffffffu, s, off);
            ss += __shfl_xor_sync(0xffffffffu, ss, off);
        }
        if (lane == 0) {
            float mu = s * (1.f / BOND);
            mu_s[w] = mu;
            rs_s[w] = rsqrtf(ss * (1.f / BOND) - mu * mu + 1e-5f);
        }
    }
    __syncthreads();

    for (int idx = tid; idx < BB * BOND; idx += 512) {
        int bb = idx >> 7, c = idx & 127;
        hs[bb][c] = (hs[bb][c] - mu_s[bb]) * rs_s[bb] * gamma[c] + beta[c];
    }
    __syncthreads();

    const int e = tid;
    float acc[BB];
    float bhe = bh[e];
#pragma unroll
    for (int j = 0; j < BB; j++) acc[j] = bhe;

#pragma unroll 8
    for (int c = 0; c < BOND; c++) {
        float wv = Wh[(size_t)c * EMB + e];
#pragma unroll
        for (int j = 0; j < BB; j++) acc[j] += hs[j][c] * wv;
    }
#pragma unroll
    for (int j = 0; j < BB; j++) outs[j][e] = acc[j];
    __syncthreads();

    if (w < BB) {
        float ss = 0.f;
        for (int ee = lane; ee < EMB; ee += 32) {
            float v = outs[w][ee]; ss += v * v;
        }
#pragma unroll
        for (int off = 16; off; off >>= 1)
            ss += __shfl_xor_sync(0xffffffffu, ss, off);
        if (lane == 0)
            rn_s[w] = 1.f / fmaxf(sqrtf(ss), 1e-12f);
    }
    __syncthreads();

    for (int idx = tid; idx < BB * EMB; idx += 512) {
        int bb = idx >> 9, ee = idx & 511;
        outg[(size_t)(b0 + bb) * EMB + ee] = outs[bb][ee] * rn_s[bb];
    }
}

// ============================================================================
// launch
// ============================================================================
extern "C" void kernel_launch(void* const* d_in, const int* in_sizes, int n_in,
                              void* d_out, int out_size)
{
    // Input ordering: metadata follows setup_inputs() dict insertion order:
    //   x, W_patch, b_patch, pos, gamma, beta, W_head, b_head,
    //   f0, o0, f1, o1, f2, o2, f3, o3
    // Fall back to reference-signature order if sizes say otherwise.
    // Discriminator: slot 4 is gamma (128 elems) in dict order, f0 (2097152) in
    // signature order.
    const float *x, *Wp, *bp, *pos, *gamma, *beta, *Wh, *bh;
    const float *f0, *o0, *f1, *o1, *f2, *o2, *f3, *o3;

    x  = (const float*)d_in[0];
    Wp = (const float*)d_in[1];
    bp = (const float*)d_in[2];
    pos= (const float*)d_in[3];
    if (in_sizes[4] == BOND) {
        // dict order
        gamma = (const float*)d_in[4];
        beta  = (const float*)d_in[5];
        Wh    = (const float*)d_in[6];
        bh    = (const float*)d_in[7];
        f0    = (const float*)d_in[8];
        o0    = (const float*)d_in[9];
        f1    = (const float*)d_in[10];
        o1    = (const float*)d_in[11];
        f2    = (const float*)d_in[12];
        o2    = (const float*)d_in[13];
        f3    = (const float*)d_in[14];
        o3    = (const float*)d_in[15];
    } else {
        // reference signature order
        f0    = (const float*)d_in[4];
        o0    = (const float*)d_in[5];
        f1    = (const float*)d_in[6];
        o1    = (const float*)d_in[7];
        f2    = (const float*)d_in[8];
        o2    = (const float*)d_in[9];
        f3    = (const float*)d_in[10];
        o3    = (const float*)d_in[11];
        gamma = (const float*)d_in[12];
        beta  = (const float*)d_in[13];
        Wh    = (const float*)d_in[14];
        bh    = (const float*)d_in[15];
    }
    float* outp = (float*)d_out;

    const int SM_K1    = (128 * 65 + 64 * 128) * (int)sizeof(float);   // 66048
    const int SM_CP128 = (128 * 129 + 128 * 64) * (int)sizeof(float);  // 98816
    const int SM_CP32  = (32 * 129 + 128 * 64) * (int)sizeof(float);   // 49280

    cudaFuncSetAttribute((const void*)patch_embed_kernel,
                         cudaFuncAttributeMaxDynamicSharedMemorySize, SM_K1);
    cudaFuncSetAttribute((const void*)cp_level_kernel<128>,
                         cudaFuncAttributeMaxDynamicSharedMemorySize, SM_CP128);
    cudaFuncSetAttribute((const void*)cp_level_kernel<32>,
                         cudaFuncAttributeMaxDynamicSharedMemorySize, SM_CP32);

    float *h0, *h1, *h2, *h3, *h4;
    cudaGetSymbolAddress((void**)&h0, g_h0);
    cudaGetSymbolAddress((void**)&h1, g_h1);
    cudaGetSymbolAddress((void**)&h2, g_h2);
    cudaGetSymbolAddress((void**)&h3, g_h3);
    cudaGetSymbolAddress((void**)&h4, g_h4);

    patch_embed_kernel<<<1024, 256, SM_K1>>>(x, Wp, bp, pos);

    cp_level_kernel<128><<<dim3(BATCH / 128, 64), 256, SM_CP128>>>(h0, h1, f0, o0, 16);
    cp_level_kernel<32> <<<dim3(BATCH / 32, 16), 256, SM_CP32 >>>(h1, h2, f1, o1, 8);
    cp_level_kernel<32> <<<dim3(BATCH / 32, 4),  256, SM_CP32 >>>(h2, h3, f2, o2, 4);
    cp_level_kernel<32> <<<dim3(BATCH / 32, 1),  256, SM_CP32 >>>(h3, h4, f3, o3, 2);

    head_kernel<<<BATCH / 8, 512>>>(gamma, beta, Wh, bh, outp);
}

// round 13
// speedup vs baseline: 1.4374x; 1.4374x over previous
#include <cuda_runtime.h>
#include <cstdint>

#define BATCH     512
#define NP        256        // 16*16 patches
#define BOND      128
#define RANK      64
#define EMB       512

// ---------------- scratch (static device globals: allocation-free) ----------
__device__ float g_h0[BATCH * NP * BOND];   // 67 MB
__device__ float g_h1[BATCH * 64 * BOND];
__device__ float g_h2[BATCH * 16 * BOND];
__device__ float g_h3[BATCH * 4  * BOND];
__device__ float g_h4[BATCH * 1  * BOND];

// ============================================================================
// K1: patchify + patch GEMM + bias + pos  (unchanged from passing R12 kernel)
// ============================================================================
__global__ void __launch_bounds__(256)
patch_embed_kernel(const float* __restrict__ x,
                   const float* __restrict__ Wp,
                   const float* __restrict__ bp,
                   const float* __restrict__ pos)
{
    extern __shared__ float sm[];
    float* As = sm;                 // [128][65]
    float* Ws = sm + 128 * 65;      // [64][128]

    const int tid = threadIdx.x;
    const int r0  = blockIdx.x * 128;

    for (int idx = tid; idx < 128 * 64; idx += 256) {
        int i = idx >> 6;
        int k = idx & 63;
        int row = r0 + i;
        int b = row >> 8, p = row & 255;
        int gy = p >> 4, gx = p & 15;
        int py = k >> 3, px = k & 7;
        As[i * 65 + k] = x[(b * 128 + gy * 8 + py) * 128 + gx * 8 + px];
    }
    for (int idx = tid; idx < 64 * 128; idx += 256)
        Ws[idx] = Wp[idx];
    __syncthreads();

    const int rg = tid >> 4;
    const int cg = tid & 15;

    float acc[8][8];
#pragma unroll
    for (int j = 0; j < 8; j++)
#pragma unroll
        for (int i = 0; i < 8; i++) acc[j][i] = 0.f;

#pragma unroll 8
    for (int k = 0; k < 64; k++) {
        float4 w0 = *(const float4*)(Ws + k * 128 + cg * 8);
        float4 w1 = *(const float4*)(Ws + k * 128 + cg * 8 + 4);
        float a[8];
#pragma unroll
        for (int j = 0; j < 8; j++) a[j] = As[(rg * 8 + j) * 65 + k];
#pragma unroll
        for (int j = 0; j < 8; j++) {
            acc[j][0] += a[j] * w0.x; acc[j][1] += a[j] * w0.y;
            acc[j][2] += a[j] * w0.z; acc[j][3] += a[j] * w0.w;
            acc[j][4] += a[j] * w1.x; acc[j][5] += a[j] * w1.y;
            acc[j][6] += a[j] * w1.z; acc[j][7] += a[j] * w1.w;
        }
    }

    float4 bp0 = *(const float4*)(bp + cg * 8);
    float4 bp1 = *(const float4*)(bp + cg * 8 + 4);
#pragma unroll
    for (int j = 0; j < 8; j++) {
        int row = r0 + rg * 8 + j;
        int p = row & 255;
        float4 p0 = *(const float4*)(pos + p * 128 + cg * 8);
        float4 p1 = *(const float4*)(pos + p * 128 + cg * 8 + 4);
        float4 o0, o1;
        o0.x = acc[j][0] + bp0.x + p0.x; o0.y = acc[j][1] + bp0.y + p0.y;
        o0.z = acc[j][2] + bp0.z + p0.z; o0.w = acc[j][3] + bp0.w + p0.w;
        o1.x = acc[j][4] + bp1.x + p1.x; o1.y = acc[j][5] + bp1.y + p1.y;
        o1.z = acc[j][6] + bp1.z + p1.z; o1.w = acc[j][7] + bp1.w + p1.w;
        *(float4*)(g_h0 + (size_t)row * 128 + cg * 8)     = o0;
        *(float4*)(g_h0 + (size_t)row * 128 + cg * 8 + 4) = o1;
    }
}

// ============================================================================
// K2 v2: one CP-tree level, all levels.
//   grid (BATCH/32, nodes), 256 threads = 4 quad-groups x 64.
//   Group q: U_q[32 rows x 64 ranks], thread tile M=8 rows x N=4 ranks.
//   F streamed in k-chunks of 32; X staged once. Then P = prod_q U_q, out = P@O.
// ============================================================================
__global__ void __launch_bounds__(256)
cp_level_v2(const float* __restrict__ in,
            float* __restrict__ out,
            const float* __restrict__ f,
            const float* __restrict__ o,
            int g)   // input grid size
{
    constexpr int TB = 32;

    extern __shared__ float sm[];
    float* Xs = sm;                       // [4][32][129] = 16512 floats
    float* Fs = sm + 4 * TB * 129;        // [4][32][64]  =  8192 floats
    float* Us = sm;                       // alias Xs: [4][32][65] = 8320 floats
    float* Ps = sm + 4 * TB * 65;         // alias Xs: [32][65] at 8320..10400
    float* Os = Fs;                       // alias Fs: [64][128] = 8192 floats

    const int t    = threadIdx.x;
    const int q    = t >> 6;              // quad group 0..3
    const int tg   = t & 63;
    const int bg   = tg >> 4;             // 0..3  -> rows bg*8 .. bg*8+7
    const int rg   = tg & 15;             // 0..15 -> ranks rg*4 .. rg*4+3

    const int node = blockIdx.y;
    const int b0   = blockIdx.x * TB;
    const int g2   = g >> 1;
    const int ny   = node / g2, nx = node % g2;
    const size_t inStride  = (size_t)g * g * BOND;
    const size_t outStride = (size_t)g2 * g2 * BOND;

    const int child = (2 * ny + (q >> 1)) * g + (2 * nx + (q & 1));
    const float* xin = in + (size_t)child * BOND;
    const float* fq  = f + (size_t)(node * 4 + q) * (BOND * RANK);
    float* Xq = Xs + q * (TB * 129);
    float* Fq = Fs + q * (32 * RANK);

    // stage X for this quad: 32 rows x 128, coalesced on k
    for (int i = tg; i < TB * 128; i += 64) {
        int row = i >> 7, k = i & 127;
        Xq[row * 129 + k] = xin[(size_t)(b0 + row) * inStride + k];
    }

    float u[8][4];
#pragma unroll
    for (int j = 0; j < 8; j++)
#pragma unroll
        for (int i = 0; i < 4; i++) u[j][i] = 0.f;

    for (int c0 = 0; c0 < 128; c0 += 32) {
        __syncthreads();                          // Xs ready / prior Fs reads done
        // stage F chunk for this quad: 32 x 64 floats = 512 float4
        {
            const float4* src4 = (const float4*)(fq + c0 * RANK);
            float4* dst4 = (float4*)Fq;
            for (int i = tg; i < 512; i += 64) dst4[i] = src4[i];
        }
        __syncthreads();

#pragma unroll 4
        for (int kk = 0; kk < 32; kk++) {
            float4 fv = *(const float4*)(Fq + kk * RANK + rg * 4);
            float a[8];
#pragma unroll
            for (int j = 0; j < 8; j++) a[j] = Xq[(bg * 8 + j) * 129 + c0 + kk];
#pragma unroll
            for (int j = 0; j < 8; j++) {
                u[j][0] += a[j] * fv.x; u[j][1] += a[j] * fv.y;
                u[j][2] += a[j] * fv.z; u[j][3] += a[j] * fv.w;
            }
        }
    }

    __syncthreads();    // all Xs / Fs reads complete

    // write U for this quad (overlaps old Xs region)
    {
        float* Uq = Us + q * (TB * 65);
#pragma unroll
        for (int j = 0; j < 8; j++)
#pragma unroll
            for (int i = 0; i < 4; i++)
                Uq[(bg * 8 + j) * 65 + rg * 4 + i] = u[j][i];
    }
    // load O (overwrites Fs region — safe after sync above)
    {
        const float4* ob4 = (const float4*)(o + (size_t)node * (RANK * BOND));
        float4* Os4 = (float4*)Os;
        for (int i = t; i < (RANK * BOND) / 4; i += 256) Os4[i] = ob4[i];
    }
    __syncthreads();

    // P = prod over quads
    for (int idx = t; idx < TB * RANK; idx += 256) {
        int row = idx >> 6, r = idx & 63;
        float pp = Us[0 * (TB * 65) + row * 65 + r]
                 * Us[1 * (TB * 65) + row * 65 + r]
                 * Us[2 * (TB * 65) + row * 65 + r]
                 * Us[3 * (TB * 65) + row * 65 + r];
        Ps[row * 65 + r] = pp;
    }
    __syncthreads();

    // out[b, node, :] = P @ O   (32 x 128, thread tile 2 rows x 8 cols)
    const int bg2 = t >> 4;       // 0..15 -> rows bg2*2, bg2*2+1
    const int cg  = t & 15;       // 0..15 -> cols cg*8 .. cg*8+7

    float acc[2][8];
#pragma unroll
    for (int j = 0; j < 2; j++)
#pragma unroll
        for (int i = 0; i < 8; i++) acc[j][i] = 0.f;

#pragma unroll 8
    for (int r = 0; r < 64; r++) {
        float4 w0 = *(const float4*)(Os + r * 128 + cg * 8);
        float4 w1 = *(const float4*)(Os + r * 128 + cg * 8 + 4);
        float a0 = Ps[(bg2 * 2)     * 65 + r];
        float a1 = Ps[(bg2 * 2 + 1) * 65 + r];
        acc[0][0] += a0 * w0.x; acc[0][1] += a0 * w0.y;
        acc[0][2] += a0 * w0.z; acc[0][3] += a0 * w0.w;
        acc[0][4] += a0 * w1.x; acc[0][5] += a0 * w1.y;
        acc[0][6] += a0 * w1.z; acc[0][7] += a0 * w1.w;
        acc[1][0] += a1 * w0.x; acc[1][1] += a1 * w0.y;
        acc[1][2] += a1 * w0.z; acc[1][3] += a1 * w0.w;
        acc[1][4] += a1 * w1.x; acc[1][5] += a1 * w1.y;
        acc[1][6] += a1 * w1.z; acc[1][7] += a1 * w1.w;
    }

#pragma unroll
    for (int j = 0; j < 2; j++) {
        int b = b0 + bg2 * 2 + j;
        float* op = out + (size_t)b * outStride + (size_t)node * BOND + cg * 8;
        float4 s0, s1;
        s0.x = acc[j][0]; s0.y = acc[j][1]; s0.z = acc[j][2]; s0.w = acc[j][3];
        s1.x = acc[j][4]; s1.y = acc[j][5]; s1.z = acc[j][6]; s1.w = acc[j][7];
        *(float4*)(op)     = s0;
        *(float4*)(op + 4) = s1;
    }
}

// ============================================================================
// K3: LayerNorm + head GEMM + row L2-normalize (unchanged)
// ============================================================================
__global__ void __launch_bounds__(512)
head_kernel(const float* __restrict__ gamma,
            const float* __restrict__ beta,
            const float* __restrict__ Wh,
            const float* __restrict__ bh,
            float* __restrict__ outg)
{
    constexpr int BB = 8;
    __shared__ float hs[BB][BOND];
    __shared__ float outs[BB][EMB];
    __shared__ float mu_s[BB], rs_s[BB], rn_s[BB];

    const int tid = threadIdx.x;
    const int b0  = blockIdx.x * BB;
    const int w   = tid >> 5, lane = tid & 31;

    for (int idx = tid; idx < BB * BOND; idx += 512)
        hs[idx >> 7][idx & 127] = g_h4[(size_t)(b0 + (idx >> 7)) * BOND + (idx & 127)];
    __syncthreads();

    if (w < BB) {
        float s = 0.f, ss = 0.f;
        for (int c = lane; c < BOND; c += 32) {
            float v = hs[w][c]; s += v; ss += v * v;
        }
#pragma unroll
        for (int off = 16; off; off >>= 1) {
            s  += __shfl_xor_sync(0xffffffffu, s, off);
            ss += __shfl_xor_sync(0xffffffffu, ss, off);
        }
        if (lane == 0) {
            float mu = s * (1.f / BOND);
            mu_s[w] = mu;
            rs_s[w] = rsqrtf(ss * (1.f / BOND) - mu * mu + 1e-5f);
        }
    }
    __syncthreads();

    for (int idx = tid; idx < BB * BOND; idx += 512) {
        int bb = idx >> 7, c = idx & 127;
        hs[bb][c] = (hs[bb][c] - mu_s[bb]) * rs_s[bb] * gamma[c] + beta[c];
    }
    __syncthreads();

    const int e = tid;
    float acc[BB];
    float bhe = bh[e];
#pragma unroll
    for (int j = 0; j < BB; j++) acc[j] = bhe;

#pragma unroll 8
    for (int c = 0; c < BOND; c++) {
        float wv = Wh[(size_t)c * EMB + e];
#pragma unroll
        for (int j = 0; j < BB; j++) acc[j] += hs[j][c] * wv;
    }
#pragma unroll
    for (int j = 0; j < BB; j++) outs[j][e] = acc[j];
    __syncthreads();

    if (w < BB) {
        float ss = 0.f;
        for (int ee = lane; ee < EMB; ee += 32) {
            float v = outs[w][ee]; ss += v * v;
        }
#pragma unroll
        for (int off = 16; off; off >>= 1)
            ss += __shfl_xor_sync(0xffffffffu, ss, off);
        if (lane == 0)
            rn_s[w] = 1.f / fmaxf(sqrtf(ss), 1e-12f);
    }
    __syncthreads();

    for (int idx = tid; idx < BB * EMB; idx += 512) {
        int bb = idx >> 9, ee = idx & 511;
        outg[(size_t)(b0 + bb) * EMB + ee] = outs[bb][ee] * rn_s[bb];
    }
}

// ============================================================================
// launch
// ============================================================================
extern "C" void kernel_launch(void* const* d_in, const int* in_sizes, int n_in,
                              void* d_out, int out_size)
{
    // metadata follows setup_inputs() dict insertion order; keep the size-based
    // discriminator as a safety net (slot 4: gamma=128 vs f0=2097152).
    const float *x, *Wp, *bp, *pos, *gamma, *beta, *Wh, *bh;
    const float *f0, *o0, *f1, *o1, *f2, *o2, *f3, *o3;

    x   = (const float*)d_in[0];
    Wp  = (const float*)d_in[1];
    bp  = (const float*)d_in[2];
    pos = (const float*)d_in[3];
    if (in_sizes[4] == BOND) {
        gamma = (const float*)d_in[4];  beta = (const float*)d_in[5];
        Wh    = (const float*)d_in[6];  bh   = (const float*)d_in[7];
        f0 = (const float*)d_in[8];   o0 = (const float*)d_in[9];
        f1 = (const float*)d_in[10];  o1 = (const float*)d_in[11];
        f2 = (const float*)d_in[12];  o2 = (const float*)d_in[13];
        f3 = (const float*)d_in[14];  o3 = (const float*)d_in[15];
    } else {
        f0 = (const float*)d_in[4];   o0 = (const float*)d_in[5];
        f1 = (const float*)d_in[6];   o1 = (const float*)d_in[7];
        f2 = (const float*)d_in[8];   o2 = (const float*)d_in[9];
        f3 = (const float*)d_in[10];  o3 = (const float*)d_in[11];
        gamma = (const float*)d_in[12]; beta = (const float*)d_in[13];
        Wh    = (const float*)d_in[14]; bh   = (const float*)d_in[15];
    }
    float* outp = (float*)d_out;

    const int SM_K1 = (128 * 65 + 64 * 128) * (int)sizeof(float);      // 66048
    const int SM_CP = (4 * 32 * 129 + 4 * 32 * 64) * (int)sizeof(float); // 98816

    cudaFuncSetAttribute((const void*)patch_embed_kernel,
                         cudaFuncAttributeMaxDynamicSharedMemorySize, SM_K1);
    cudaFuncSetAttribute((const void*)cp_level_v2,
                         cudaFuncAttributeMaxDynamicSharedMemorySize, SM_CP);

    float *h0, *h1, *h2, *h3, *h4;
    cudaGetSymbolAddress((void**)&h0, g_h0);
    cudaGetSymbolAddress((void**)&h1, g_h1);
    cudaGetSymbolAddress((void**)&h2, g_h2);
    cudaGetSymbolAddress((void**)&h3, g_h3);
    cudaGetSymbolAddress((void**)&h4, g_h4);

    patch_embed_kernel<<<1024, 256, SM_K1>>>(x, Wp, bp, pos);

    cp_level_v2<<<dim3(BATCH / 32, 64), 256, SM_CP>>>(h0, h1, f0, o0, 16);
    cp_level_v2<<<dim3(BATCH / 32, 16), 256, SM_CP>>>(h1, h2, f1, o1, 8);
    cp_level_v2<<<dim3(BATCH / 32, 4),  256, SM_CP>>>(h2, h3, f2, o2, 4);
    cp_level_v2<<<dim3(BATCH / 32, 1),  256, SM_CP>>>(h3, h4, f3, o3, 2);

    head_kernel<<<BATCH / 8, 512>>>(gamma, beta, Wh, bh, outp);
}

// round 14
// speedup vs baseline: 1.5487x; 1.0774x over previous
#include <cuda_runtime.h>
#include <cstdint>

#define BATCH     512
#define NP        256
#define BOND      128
#define RANK      64
#define EMB       512

// packed fp32x2 helpers ------------------------------------------------------
#define FMA2(d, a, b) \
    asm("fma.rn.f32x2 %0, %1, %2, %0;" : "+l"(d) : "l"(a), "l"(b))
#define BCAST2(d, s) \
    asm("mov.b64 %0, {%1, %1};" : "=l"(d) : "r"(__float_as_uint(s)))
#define UNPK2(lo, hi, s) \
    asm("mov.b64 {%0, %1}, %2;" : "=r"(lo), "=r"(hi) : "l"(s))

// ---------------- scratch (static device globals: allocation-free) ----------
__device__ float g_h0[BATCH * NP * BOND];   // 67 MB
__device__ float g_h1[BATCH * 64 * BOND];
__device__ float g_h2[BATCH * 16 * BOND];
__device__ float g_h3[BATCH * 4  * BOND];
__device__ float g_h4[BATCH * 1  * BOND];

// ============================================================================
// K1: patchify + patch GEMM + bias + pos.
//   A staged k-major (transposed) [64][132]; inner loop 4 LDS.128 + 32 FMA2.
// ============================================================================
__global__ void __launch_bounds__(256)
patch_embed_kernel(const float* __restrict__ x,
                   const float* __restrict__ Wp,
                   const float* __restrict__ bp,
                   const float* __restrict__ pos)
{
    extern __shared__ float sm[];
    float* At = sm;                 // [64][132]  (k-major, stride 132)
    float* Ws = sm + 64 * 132;      // [64][128]

    const int tid = threadIdx.x;
    const int r0  = blockIdx.x * 128;

    // stage A transposed: At[k*132 + row]
    for (int idx = tid; idx < 128 * 64; idx += 256) {
        int i = idx >> 6;           // row within block (0..127)
        int k = idx & 63;           // pixel within patch
        int row = r0 + i;
        int b = row >> 8, p = row & 255;
        int gy = p >> 4, gx = p & 15;
        int py = k >> 3, px = k & 7;
        At[k * 132 + i] = x[(b * 128 + gy * 8 + py) * 128 + gx * 8 + px];
    }
    for (int idx = tid; idx < 64 * 128; idx += 256)
        Ws[idx] = Wp[idx];
    __syncthreads();

    const int rg = tid >> 4;        // 16 row groups of 8
    const int cg = tid & 15;        // 16 col groups of 8

    unsigned long long acc2[8][4];
#pragma unroll
    for (int j = 0; j < 8; j++)
#pragma unroll
        for (int i = 0; i < 4; i++) acc2[j][i] = 0ULL;

#pragma unroll 4
    for (int k = 0; k < 64; k++) {
        ulonglong2 w01 = *(const ulonglong2*)(Ws + k * 128 + cg * 8);
        ulonglong2 w23 = *(const ulonglong2*)(Ws + k * 128 + cg * 8 + 4);
        float4 a0 = *(const float4*)(At + k * 132 + rg * 8);
        float4 a1 = *(const float4*)(At + k * 132 + rg * 8 + 4);
        float a[8] = {a0.x, a0.y, a0.z, a0.w, a1.x, a1.y, a1.z, a1.w};
#pragma unroll
        for (int j = 0; j < 8; j++) {
            unsigned long long aa;
            BCAST2(aa, a[j]);
            FMA2(acc2[j][0], aa, w01.x);
            FMA2(acc2[j][1], aa, w01.y);
            FMA2(acc2[j][2], aa, w23.x);
            FMA2(acc2[j][3], aa, w23.y);
        }
    }

    float4 bp0 = *(const float4*)(bp + cg * 8);
    float4 bp1 = *(const float4*)(bp + cg * 8 + 4);
#pragma unroll
    for (int j = 0; j < 8; j++) {
        int row = r0 + rg * 8 + j;
        int p = row & 255;
        float4 p0 = *(const float4*)(pos + p * 128 + cg * 8);
        float4 p1 = *(const float4*)(pos + p * 128 + cg * 8 + 4);
        unsigned v[8];
#pragma unroll
        for (int i = 0; i < 4; i++) UNPK2(v[2 * i], v[2 * i + 1], acc2[j][i]);
        float4 o0, o1;
        o0.x = __uint_as_float(v[0]) + bp0.x + p0.x;
        o0.y = __uint_as_float(v[1]) + bp0.y + p0.y;
        o0.z = __uint_as_float(v[2]) + bp0.z + p0.z;
        o0.w = __uint_as_float(v[3]) + bp0.w + p0.w;
        o1.x = __uint_as_float(v[4]) + bp1.x + p1.x;
        o1.y = __uint_as_float(v[5]) + bp1.y + p1.y;
        o1.z = __uint_as_float(v[6]) + bp1.z + p1.z;
        o1.w = __uint_as_float(v[7]) + bp1.w + p1.w;
        *(float4*)(g_h0 + (size_t)row * 128 + cg * 8)     = o0;
        *(float4*)(g_h0 + (size_t)row * 128 + cg * 8 + 4) = o1;
    }
}

// ============================================================================
// K2 v3: one CP-tree level. grid (BATCH/TB, nodes), 256 thr = 4 quads x 64.
//   X staged k-major; inner loop: 1 LDS.128 (F) + vec LDS (X) + M*2 FMA2.
// ============================================================================
template <int TB>
__global__ void __launch_bounds__(256)
cp_level_v3(const float* __restrict__ in,
            float* __restrict__ out,
            const float* __restrict__ f,
            const float* __restrict__ o,
            int g)   // input grid size
{
    constexpr int M  = TB / 4;       // rows per thread, phase 1
    constexpr int XS = TB + 4;       // Xt row stride (mult of 4 floats)
    constexpr int CK = 32;           // F k-chunk

    extern __shared__ float sm[];
    float* Xt = sm;                        // [4][128][XS]
    float* Fs = sm + 4 * 128 * XS;         // [4][CK][64] = 8192 floats
    float* Us = sm;                        // alias: [4][TB][68]
    float* Ps = sm + 4 * TB * 68;          // alias: [TB][68]
    float* Os = Fs;                        // alias: [64][128] = 8192 floats

    const int t  = threadIdx.x;
    const int q  = t >> 6;
    const int tg = t & 63;
    const int bg = tg >> 4;          // 0..3
    const int rg = tg & 15;          // 0..15

    const int node = blockIdx.y;
    const int b0   = blockIdx.x * TB;
    const int g2   = g >> 1;
    const int ny   = node / g2, nx = node % g2;
    const size_t inStride  = (size_t)g * g * BOND;
    const size_t outStride = (size_t)g2 * g2 * BOND;

    const int child = (2 * ny + (q >> 1)) * g + (2 * nx + (q & 1));
    const float* xin = in + (size_t)child * BOND;
    const float* fq  = f + (size_t)(node * 4 + q) * (BOND * RANK);
    float* Xq = Xt + q * 128 * XS;
    float* Fq = Fs + q * CK * 64;

    // stage X transposed: Xq[k*XS + row], gmem coalesced on k
    for (int i = tg; i < TB * 128; i += 64) {
        int row = i >> 7, k = i & 127;
        Xq[k * XS + row] = xin[(size_t)(b0 + row) * inStride + k];
    }

    unsigned long long u2[M][2];
#pragma unroll
    for (int j = 0; j < M; j++) { u2[j][0] = 0ULL; u2[j][1] = 0ULL; }

    for (int c0 = 0; c0 < 128; c0 += CK) {
        __syncthreads();                       // Xt ready / prior F reads done
        {
            const float4* s4 = (const float4*)(fq + c0 * RANK);
            float4* d4 = (float4*)Fq;
            for (int i = tg; i < CK * 16; i += 64) d4[i] = s4[i];
        }
        __syncthreads();

#pragma unroll 4
        for (int kk = 0; kk < CK; kk++) {
            ulonglong2 fv = *(const ulonglong2*)(Fq + kk * RANK + rg * 4);
            const float* xrow = Xq + (c0 + kk) * XS + bg * M;
            float a[M];
            if constexpr (M == 8) {
                float4 x0 = *(const float4*)(xrow);
                float4 x1 = *(const float4*)(xrow + 4);
                a[0] = x0.x; a[1] = x0.y; a[2] = x0.z; a[3] = x0.w;
                a[4] = x1.x; a[5] = x1.y; a[6] = x1.z; a[7] = x1.w;
            } else if constexpr (M == 2) {
                float2 x0 = *(const float2*)(xrow);
                a[0] = x0.x; a[1] = x0.y;
            } else {
                a[0] = xrow[0];
            }
#pragma unroll
            for (int j = 0; j < M; j++) {
                unsigned long long aa;
                BCAST2(aa, a[j]);
                FMA2(u2[j][0], aa, fv.x);
                FMA2(u2[j][1], aa, fv.y);
            }
        }
    }

    __syncthreads();    // all Xt/Fs reads complete before aliasing

    // write U (ranks rg*4..+3 for rows bg*M..)
    {
        float* Uq = Us + q * TB * 68;
#pragma unroll
        for (int j = 0; j < M; j++) {
            unsigned v0, v1, v2, v3;
            UNPK2(v0, v1, u2[j][0]);
            UNPK2(v2, v3, u2[j][1]);
            float4 s;
            s.x = __uint_as_float(v0); s.y = __uint_as_float(v1);
            s.z = __uint_as_float(v2); s.w = __uint_as_float(v3);
            *(float4*)(Uq + (bg * M + j) * 68 + rg * 4) = s;
        }
    }
    // load O (overwrites Fs)
    {
        const float4* ob4 = (const float4*)(o + (size_t)node * (RANK * BOND));
        float4* Os4 = (float4*)Os;
        for (int i = t; i < (RANK * BOND) / 4; i += 256) Os4[i] = ob4[i];
    }
    __syncthreads();

    // P = prod over quads
    for (int idx = t; idx < TB * RANK; idx += 256) {
        int row = idx >> 6, r = idx & 63;
        Ps[row * 68 + r] = Us[0 * TB * 68 + row * 68 + r]
                         * Us[1 * TB * 68 + row * 68 + r]
                         * Us[2 * TB * 68 + row * 68 + r]
                         * Us[3 * TB * 68 + row * 68 + r];
    }
    __syncthreads();

    // phase 2: out = P @ O  (TB x 128)
    if constexpr (TB >= 32) {
        const int bg2 = t >> 4;      // 0..15 -> 2 rows each
        const int cg  = t & 15;      // 8 cols each
        unsigned long long acc2[2][4];
#pragma unroll
        for (int j = 0; j < 2; j++)
#pragma unroll
            for (int i = 0; i < 4; i++) acc2[j][i] = 0ULL;

#pragma unroll 8
        for (int r = 0; r < RANK; r++) {
            ulonglong2 w01 = *(const ulonglong2*)(Os + r * 128 + cg * 8);
            ulonglong2 w23 = *(const ulonglong2*)(Os + r * 128 + cg * 8 + 4);
            float a0 = Ps[(bg2 * 2)     * 68 + r];
            float a1 = Ps[(bg2 * 2 + 1) * 68 + r];
            unsigned long long aa0, aa1;
            BCAST2(aa0, a0);
            BCAST2(aa1, a1);
            FMA2(acc2[0][0], aa0, w01.x); FMA2(acc2[0][1], aa0, w01.y);
            FMA2(acc2[0][2], aa0, w23.x); FMA2(acc2[0][3], aa0, w23.y);
            FMA2(acc2[1][0], aa1, w01.x); FMA2(acc2[1][1], aa1, w01.y);
            FMA2(acc2[1][2], aa1, w23.x); FMA2(acc2[1][3], aa1, w23.y);
        }

#pragma unroll
        for (int j = 0; j < 2; j++) {
            int b = b0 + bg2 * 2 + j;
            float* op = out + (size_t)b * outStride + (size_t)node * BOND + cg * 8;
            unsigned v[8];
#pragma unroll
            for (int i = 0; i < 4; i++) UNPK2(v[2 * i], v[2 * i + 1], acc2[j][i]);
            float4 s0, s1;
            s0.x = __uint_as_float(v[0]); s0.y = __uint_as_float(v[1]);
            s0.z = __uint_as_float(v[2]); s0.w = __uint_as_float(v[3]);
            s1.x = __uint_as_float(v[4]); s1.y = __uint_as_float(v[5]);
            s1.z = __uint_as_float(v[6]); s1.w = __uint_as_float(v[7]);
            *(float4*)(op)     = s0;
            *(float4*)(op + 4) = s1;
        }
    } else {
        // small levels: generic scalar phase 2 (tiny work)
        for (int idx = t; idx < TB * 128; idx += 256) {
            int row = idx >> 7, c = idx & 127;
            float acc = 0.f;
#pragma unroll 8
            for (int r = 0; r < RANK; r++)
                acc += Ps[row * 68 + r] * Os[r * 128 + c];
            out[(size_t)(b0 + row) * outStride + (size_t)node * BOND + c] = acc;
        }
    }
}

// ============================================================================
// K3: LayerNorm + head GEMM + row L2-normalize (unchanged)
// ============================================================================
__global__ void __launch_bounds__(512)
head_kernel(const float* __restrict__ gamma,
            const float* __restrict__ beta,
            const float* __restrict__ Wh,
            const float* __restrict__ bh,
            float* __restrict__ outg)
{
    constexpr int BB = 8;
    __shared__ float hs[BB][BOND];
    __shared__ float outs[BB][EMB];
    __shared__ float mu_s[BB], rs_s[BB], rn_s[BB];

    const int tid = threadIdx.x;
    const int b0  = blockIdx.x * BB;
    const int w   = tid >> 5, lane = tid & 31;

    for (int idx = tid; idx < BB * BOND; idx += 512)
        hs[idx >> 7][idx & 127] = g_h4[(size_t)(b0 + (idx >> 7)) * BOND + (idx & 127)];
    __syncthreads();

    if (w < BB) {
        float s = 0.f, ss = 0.f;
        for (int c = lane; c < BOND; c += 32) {
            float v = hs[w][c]; s += v; ss += v * v;
        }
#pragma unroll
        for (int off = 16; off; off >>= 1) {
            s  += __shfl_xor_sync(0xffffffffu, s, off);
            ss += __shfl_xor_sync(0xffffffffu, ss, off);
        }
        if (lane == 0) {
            float mu = s * (1.f / BOND);
            mu_s[w] = mu;
            rs_s[w] = rsqrtf(ss * (1.f / BOND) - mu * mu + 1e-5f);
        }
    }
    __syncthreads();

    for (int idx = tid; idx < BB * BOND; idx += 512) {
        int bb = idx >> 7, c = idx & 127;
        hs[bb][c] = (hs[bb][c] - mu_s[bb]) * rs_s[bb] * gamma[c] + beta[c];
    }
    __syncthreads();

    const int e = tid;
    float acc[BB];
    float bhe = bh[e];
#pragma unroll
    for (int j = 0; j < BB; j++) acc[j] = bhe;

#pragma unroll 8
    for (int c = 0; c < BOND; c++) {
        float wv = Wh[(size_t)c * EMB + e];
#pragma unroll
        for (int j = 0; j < BB; j++) acc[j] += hs[j][c] * wv;
    }
#pragma unroll
    for (int j = 0; j < BB; j++) outs[j][e] = acc[j];
    __syncthreads();

    if (w < BB) {
        float ss = 0.f;
        for (int ee = lane; ee < EMB; ee += 32) {
            float v = outs[w][ee]; ss += v * v;
        }
#pragma unroll
        for (int off = 16; off; off >>= 1)
            ss += __shfl_xor_sync(0xffffffffu, ss, off);
        if (lane == 0)
            rn_s[w] = 1.f / fmaxf(sqrtf(ss), 1e-12f);
    }
    __syncthreads();

    for (int idx = tid; idx < BB * EMB; idx += 512) {
        int bb = idx >> 9, ee = idx & 511;
        outg[(size_t)(b0 + bb) * EMB + ee] = outs[bb][ee] * rn_s[bb];
    }
}

// ============================================================================
// launch
// ============================================================================
extern "C" void kernel_launch(void* const* d_in, const int* in_sizes, int n_in,
                              void* d_out, int out_size)
{
    const float *x, *Wp, *bp, *pos, *gamma, *beta, *Wh, *bh;
    const float *f0, *o0, *f1, *o1, *f2, *o2, *f3, *o3;

    x   = (const float*)d_in[0];
    Wp  = (const float*)d_in[1];
    bp  = (const float*)d_in[2];
    pos = (const float*)d_in[3];
    if (in_sizes[4] == BOND) {          // setup_inputs() dict order
        gamma = (const float*)d_in[4];  beta = (const float*)d_in[5];
        Wh    = (const float*)d_in[6];  bh   = (const float*)d_in[7];
        f0 = (const float*)d_in[8];   o0 = (const float*)d_in[9];
        f1 = (const float*)d_in[10];  o1 = (const float*)d_in[11];
        f2 = (const float*)d_in[12];  o2 = (const float*)d_in[13];
        f3 = (const float*)d_in[14];  o3 = (const float*)d_in[15];
    } else {                            // reference-signature order fallback
        f0 = (const float*)d_in[4];   o0 = (const float*)d_in[5];
        f1 = (const float*)d_in[6];   o1 = (const float*)d_in[7];
        f2 = (const float*)d_in[8];   o2 = (const float*)d_in[9];
        f3 = (const float*)d_in[10];  o3 = (const float*)d_in[11];
        gamma = (const float*)d_in[12]; beta = (const float*)d_in[13];
        Wh    = (const float*)d_in[14]; bh   = (const float*)d_in[15];
    }
    float* outp = (float*)d_out;

    const int SM_K1   = (64 * 132 + 64 * 128) * (int)sizeof(float);        // 66560
    const int SM_CP32 = (4 * 128 * 36 + 4 * 32 * 64) * (int)sizeof(float); // 106496
    const int SM_CP8  = (4 * 128 * 12 + 4 * 32 * 64) * (int)sizeof(float); // 57344
    const int SM_CP4  = (4 * 128 * 8  + 4 * 32 * 64) * (int)sizeof(float); // 49152

    cudaFuncSetAttribute((const void*)patch_embed_kernel,
                         cudaFuncAttributeMaxDynamicSharedMemorySize, SM_K1);
    cudaFuncSetAttribute((const void*)cp_level_v3<32>,
                         cudaFuncAttributeMaxDynamicSharedMemorySize, SM_CP32);
    cudaFuncSetAttribute((const void*)cp_level_v3<8>,
                         cudaFuncAttributeMaxDynamicSharedMemorySize, SM_CP8);
    cudaFuncSetAttribute((const void*)cp_level_v3<4>,
                         cudaFuncAttributeMaxDynamicSharedMemorySize, SM_CP4);

    float *h0, *h1, *h2, *h3, *h4;
    cudaGetSymbolAddress((void**)&h0, g_h0);
    cudaGetSymbolAddress((void**)&h1, g_h1);
    cudaGetSymbolAddress((void**)&h2, g_h2);
    cudaGetSymbolAddress((void**)&h3, g_h3);
    cudaGetSymbolAddress((void**)&h4, g_h4);

    patch_embed_kernel<<<1024, 256, SM_K1>>>(x, Wp, bp, pos);

    cp_level_v3<32><<<dim3(BATCH / 32, 64), 256, SM_CP32>>>(h0, h1, f0, o0, 16);
    cp_level_v3<32><<<dim3(BATCH / 32, 16), 256, SM_CP32>>>(h1, h2, f1, o1, 8);
    cp_level_v3<8> <<<dim3(BATCH / 8,  4),  256, SM_CP8 >>>(h2, h3, f2, o2, 4);
    cp_level_v3<4> <<<dim3(BATCH / 4,  1),  256, SM_CP4 >>>(h3, h4, f3, o3, 2);

    head_kernel<<<BATCH / 8, 512>>>(gamma, beta, Wh, bh, outp);
}

// round 15
// speedup vs baseline: 1.5732x; 1.0158x over previous
#include <cuda_runtime.h>
#include <cstdint>

#define BATCH     512
#define NP        256
#define BOND      128
#define RANK      64
#define EMB       512

// packed fp32x2 helpers ------------------------------------------------------
#define FMA2(d, a, b) \
    asm("fma.rn.f32x2 %0, %1, %2, %0;" : "+l"(d) : "l"(a), "l"(b))
#define BCAST2(d, s) \
    asm("mov.b64 %0, {%1, %1};" : "=l"(d) : "r"(__float_as_uint(s)))
#define UNPK2(lo, hi, s) \
    asm("mov.b64 {%0, %1}, %2;" : "=r"(lo), "=r"(hi) : "l"(s))

// ---------------- scratch (static device globals: allocation-free) ----------
__device__ float g_h0[BATCH * NP * BOND];   // 67 MB
__device__ float g_h1[BATCH * 64 * BOND];
__device__ float g_h2[BATCH * 16 * BOND];
__device__ float g_h3[BATCH * 4  * BOND];
__device__ float g_h4[BATCH * 1  * BOND];

// ============================================================================
// K1: patchify + patch GEMM + bias + pos.
//   A staged k-major (transposed) [64][132]; inner loop 4 LDS.128 + 32 FMA2.
// ============================================================================
__global__ void __launch_bounds__(256)
patch_embed_kernel(const float* __restrict__ x,
                   const float* __restrict__ Wp,
                   const float* __restrict__ bp,
                   const float* __restrict__ pos)
{
    extern __shared__ float sm[];
    float* At = sm;                 // [64][132]  (k-major, stride 132)
    float* Ws = sm + 64 * 132;      // [64][128]

    const int tid = threadIdx.x;
    const int r0  = blockIdx.x * 128;

    // stage A transposed: At[k*132 + row]
    for (int idx = tid; idx < 128 * 64; idx += 256) {
        int i = idx >> 6;           // row within block (0..127)
        int k = idx & 63;           // pixel within patch
        int row = r0 + i;
        int b = row >> 8, p = row & 255;
        int gy = p >> 4, gx = p & 15;
        int py = k >> 3, px = k & 7;
        At[k * 132 + i] = x[(b * 128 + gy * 8 + py) * 128 + gx * 8 + px];
    }
    for (int idx = tid; idx < 64 * 128; idx += 256)
        Ws[idx] = Wp[idx];
    __syncthreads();

    const int rg = tid >> 4;        // 16 row groups of 8
    const int cg = tid & 15;        // 16 col groups of 8

    unsigned long long acc2[8][4];
#pragma unroll
    for (int j = 0; j < 8; j++)
#pragma unroll
        for (int i = 0; i < 4; i++) acc2[j][i] = 0ULL;

#pragma unroll 4
    for (int k = 0; k < 64; k++) {
        ulonglong2 w01 = *(const ulonglong2*)(Ws + k * 128 + cg * 8);
        ulonglong2 w23 = *(const ulonglong2*)(Ws + k * 128 + cg * 8 + 4);
        float4 a0 = *(const float4*)(At + k * 132 + rg * 8);
        float4 a1 = *(const float4*)(At + k * 132 + rg * 8 + 4);
        float a[8] = {a0.x, a0.y, a0.z, a0.w, a1.x, a1.y, a1.z, a1.w};
#pragma unroll
        for (int j = 0; j < 8; j++) {
            unsigned long long aa;
            BCAST2(aa, a[j]);
            FMA2(acc2[j][0], aa, w01.x);
            FMA2(acc2[j][1], aa, w01.y);
            FMA2(acc2[j][2], aa, w23.x);
            FMA2(acc2[j][3], aa, w23.y);
        }
    }

    float4 bp0 = *(const float4*)(bp + cg * 8);
    float4 bp1 = *(const float4*)(bp + cg * 8 + 4);
#pragma unroll
    for (int j = 0; j < 8; j++) {
        int row = r0 + rg * 8 + j;
        int p = row & 255;
        float4 p0 = *(const float4*)(pos + p * 128 + cg * 8);
        float4 p1 = *(const float4*)(pos + p * 128 + cg * 8 + 4);
        unsigned v[8];
#pragma unroll
        for (int i = 0; i < 4; i++) UNPK2(v[2 * i], v[2 * i + 1], acc2[j][i]);
        float4 o0, o1;
        o0.x = __uint_as_float(v[0]) + bp0.x + p0.x;
        o0.y = __uint_as_float(v[1]) + bp0.y + p0.y;
        o0.z = __uint_as_float(v[2]) + bp0.z + p0.z;
        o0.w = __uint_as_float(v[3]) + bp0.w + p0.w;
        o1.x = __uint_as_float(v[4]) + bp1.x + p1.x;
        o1.y = __uint_as_float(v[5]) + bp1.y + p1.y;
        o1.z = __uint_as_float(v[6]) + bp1.z + p1.z;
        o1.w = __uint_as_float(v[7]) + bp1.w + p1.w;
        *(float4*)(g_h0 + (size_t)row * 128 + cg * 8)     = o0;
        *(float4*)(g_h0 + (size_t)row * 128 + cg * 8 + 4) = o1;
    }
}

// ============================================================================
// K2 v3: one CP-tree level. grid (BATCH/TB, nodes), 256 thr = 4 quads x 64.
//   X staged k-major; inner loop: 1 LDS.128 (F) + vec LDS (X) + M*2 FMA2.
// ============================================================================
template <int TB>
__global__ void __launch_bounds__(256)
cp_level_v3(const float* __restrict__ in,
            float* __restrict__ out,
            const float* __restrict__ f,
            const float* __restrict__ o,
            int g)   // input grid size
{
    constexpr int M  = TB / 4;       // rows per thread, phase 1
    constexpr int XS = TB + 4;       // Xt row stride (mult of 4 floats)
    constexpr int CK = 32;           // F k-chunk

    extern __shared__ float sm[];
    float* Xt = sm;                        // [4][128][XS]
    float* Fs = sm + 4 * 128 * XS;         // [4][CK][64] = 8192 floats
    float* Us = sm;                        // alias: [4][TB][68]
    float* Ps = sm + 4 * TB * 68;          // alias: [TB][68]
    float* Os = Fs;                        // alias: [64][128] = 8192 floats

    const int t  = threadIdx.x;
    const int q  = t >> 6;
    const int tg = t & 63;
    const int bg = tg >> 4;          // 0..3
    const int rg = tg & 15;          // 0..15

    const int node = blockIdx.y;
    const int b0   = blockIdx.x * TB;
    const int g2   = g >> 1;
    const int ny   = node / g2, nx = node % g2;
    const size_t inStride  = (size_t)g * g * BOND;
    const size_t outStride = (size_t)g2 * g2 * BOND;

    const int child = (2 * ny + (q >> 1)) * g + (2 * nx + (q & 1));
    const float* xin = in + (size_t)child * BOND;
    const float* fq  = f + (size_t)(node * 4 + q) * (BOND * RANK);
    float* Xq = Xt + q * 128 * XS;
    float* Fq = Fs + q * CK * 64;

    // stage X transposed: Xq[k*XS + row], gmem coalesced on k
    for (int i = tg; i < TB * 128; i += 64) {
        int row = i >> 7, k = i & 127;
        Xq[k * XS + row] = xin[(size_t)(b0 + row) * inStride + k];
    }

    unsigned long long u2[M][2];
#pragma unroll
    for (int j = 0; j < M; j++) { u2[j][0] = 0ULL; u2[j][1] = 0ULL; }

    for (int c0 = 0; c0 < 128; c0 += CK) {
        __syncthreads();                       // Xt ready / prior F reads done
        {
            const float4* s4 = (const float4*)(fq + c0 * RANK);
            float4* d4 = (float4*)Fq;
            for (int i = tg; i < CK * 16; i += 64) d4[i] = s4[i];
        }
        __syncthreads();

#pragma unroll 4
        for (int kk = 0; kk < CK; kk++) {
            ulonglong2 fv = *(const ulonglong2*)(Fq + kk * RANK + rg * 4);
            const float* xrow = Xq + (c0 + kk) * XS + bg * M;
            float a[M];
            if constexpr (M == 8) {
                float4 x0 = *(const float4*)(xrow);
                float4 x1 = *(const float4*)(xrow + 4);
                a[0] = x0.x; a[1] = x0.y; a[2] = x0.z; a[3] = x0.w;
                a[4] = x1.x; a[5] = x1.y; a[6] = x1.z; a[7] = x1.w;
            } else if constexpr (M == 2) {
                float2 x0 = *(const float2*)(xrow);
                a[0] = x0.x; a[1] = x0.y;
            } else {
                a[0] = xrow[0];
            }
#pragma unroll
            for (int j = 0; j < M; j++) {
                unsigned long long aa;
                BCAST2(aa, a[j]);
                FMA2(u2[j][0], aa, fv.x);
                FMA2(u2[j][1], aa, fv.y);
            }
        }
    }

    __syncthreads();    // all Xt/Fs reads complete before aliasing

    // write U (ranks rg*4..+3 for rows bg*M..)
    {
        float* Uq = Us + q * TB * 68;
#pragma unroll
        for (int j = 0; j < M; j++) {
            unsigned v0, v1, v2, v3;
            UNPK2(v0, v1, u2[j][0]);
            UNPK2(v2, v3, u2[j][1]);
            float4 s;
            s.x = __uint_as_float(v0); s.y = __uint_as_float(v1);
            s.z = __uint_as_float(v2); s.w = __uint_as_float(v3);
            *(float4*)(Uq + (bg * M + j) * 68 + rg * 4) = s;
        }
    }
    // load O (overwrites Fs)
    {
        const float4* ob4 = (const float4*)(o + (size_t)node * (RANK * BOND));
        float4* Os4 = (float4*)Os;
        for (int i = t; i < (RANK * BOND) / 4; i += 256) Os4[i] = ob4[i];
    }
    __syncthreads();

    // P = prod over quads
    for (int idx = t; idx < TB * RANK; idx += 256) {
        int row = idx >> 6, r = idx & 63;
        Ps[row * 68 + r] = Us[0 * TB * 68 + row * 68 + r]
                         * Us[1 * TB * 68 + row * 68 + r]
                         * Us[2 * TB * 68 + row * 68 + r]
                         * Us[3 * TB * 68 + row * 68 + r];
    }
    __syncthreads();

    // phase 2: out = P @ O  (TB x 128)
    if constexpr (TB >= 32) {
        const int bg2 = t >> 4;      // 0..15 -> 2 rows each
        const int cg  = t & 15;      // 8 cols each
        unsigned long long acc2[2][4];
#pragma unroll
        for (int j = 0; j < 2; j++)
#pragma unroll
            for (int i = 0; i < 4; i++) acc2[j][i] = 0ULL;

#pragma unroll 8
        for (int r = 0; r < RANK; r++) {
            ulonglong2 w01 = *(const ulonglong2*)(Os + r * 128 + cg * 8);
            ulonglong2 w23 = *(const ulonglong2*)(Os + r * 128 + cg * 8 + 4);
            float a0 = Ps[(bg2 * 2)     * 68 + r];
            float a1 = Ps[(bg2 * 2 + 1) * 68 + r];
            unsigned long long aa0, aa1;
            BCAST2(aa0, a0);
            BCAST2(aa1, a1);
            FMA2(acc2[0][0], aa0, w01.x); FMA2(acc2[0][1], aa0, w01.y);
            FMA2(acc2[0][2], aa0, w23.x); FMA2(acc2[0][3], aa0, w23.y);
            FMA2(acc2[1][0], aa1, w01.x); FMA2(acc2[1][1], aa1, w01.y);
            FMA2(acc2[1][2], aa1, w23.x); FMA2(acc2[1][3], aa1, w23.y);
        }

#pragma unroll
        for (int j = 0; j < 2; j++) {
            int b = b0 + bg2 * 2 + j;
            float* op = out + (size_t)b * outStride + (size_t)node * BOND + cg * 8;
            unsigned v[8];
#pragma unroll
            for (int i = 0; i < 4; i++) UNPK2(v[2 * i], v[2 * i + 1], acc2[j][i]);
            float4 s0, s1;
            s0.x = __uint_as_float(v[0]); s0.y = __uint_as_float(v[1]);
            s0.z = __uint_as_float(v[2]); s0.w = __uint_as_float(v[3]);
            s1.x = __uint_as_float(v[4]); s1.y = __uint_as_float(v[5]);
            s1.z = __uint_as_float(v[6]); s1.w = __uint_as_float(v[7]);
            *(float4*)(op)     = s0;
            *(float4*)(op + 4) = s1;
        }
    } else {
        // small levels: generic scalar phase 2 (tiny work)
        for (int idx = t; idx < TB * 128; idx += 256) {
            int row = idx >> 7, c = idx & 127;
            float acc = 0.f;
#pragma unroll 8
            for (int r = 0; r < RANK; r++)
                acc += Ps[row * 68 + r] * Os[r * 128 + c];
            out[(size_t)(b0 + row) * outStride + (size_t)node * BOND + c] = acc;
        }
    }
}

// ============================================================================
// K3: LayerNorm + head GEMM + row L2-normalize (unchanged)
// ============================================================================
__global__ void __launch_bounds__(512)
head_kernel(const float* __restrict__ gamma,
            const float* __restrict__ beta,
            const float* __restrict__ Wh,
            const float* __restrict__ bh,
            float* __restrict__ outg)
{
    constexpr int BB = 8;
    __shared__ float hs[BB][BOND];
    __shared__ float outs[BB][EMB];
    __shared__ float mu_s[BB], rs_s[BB], rn_s[BB];

    const int tid = threadIdx.x;
    const int b0  = blockIdx.x * BB;
    const int w   = tid >> 5, lane = tid & 31;

    for (int idx = tid; idx < BB * BOND; idx += 512)
        hs[idx >> 7][idx & 127] = g_h4[(size_t)(b0 + (idx >> 7)) * BOND + (idx & 127)];
    __syncthreads();

    if (w < BB) {
        float s = 0.f, ss = 0.f;
        for (int c = lane; c < BOND; c += 32) {
            float v = hs[w][c]; s += v; ss += v * v;
        }
#pragma unroll
        for (int off = 16; off; off >>= 1) {
            s  += __shfl_xor_sync(0xffffffffu, s, off);
            ss += __shfl_xor_sync(0xffffffffu, ss, off);
        }
        if (lane == 0) {
            float mu = s * (1.f / BOND);
            mu_s[w] = mu;
            rs_s[w] = rsqrtf(ss * (1.f / BOND) - mu * mu + 1e-5f);
        }
    }
    __syncthreads();

    for (int idx = tid; idx < BB * BOND; idx += 512) {
        int bb = idx >> 7, c = idx & 127;
        hs[bb][c] = (hs[bb][c] - mu_s[bb]) * rs_s[bb] * gamma[c] + beta[c];
    }
    __syncthreads();

    const int e = tid;
    float acc[BB];
    float bhe = bh[e];
#pragma unroll
    for (int j = 0; j < BB; j++) acc[j] = bhe;

#pragma unroll 8
    for (int c = 0; c < BOND; c++) {
        float wv = Wh[(size_t)c * EMB + e];
#pragma unroll
        for (int j = 0; j < BB; j++) acc[j] += hs[j][c] * wv;
    }
#pragma unroll
    for (int j = 0; j < BB; j++) outs[j][e] = acc[j];
    __syncthreads();

    if (w < BB) {
        float ss = 0.f;
        for (int ee = lane; ee < EMB; ee += 32) {
            float v = outs[w][ee]; ss += v * v;
        }
#pragma unroll
        for (int off = 16; off; off >>= 1)
            ss += __shfl_xor_sync(0xffffffffu, ss, off);
        if (lane == 0)
            rn_s[w] = 1.f / fmaxf(sqrtf(ss), 1e-12f);
    }
    __syncthreads();

    for (int idx = tid; idx < BB * EMB; idx += 512) {
        int bb = idx >> 9, ee = idx & 511;
        outg[(size_t)(b0 + bb) * EMB + ee] = outs[bb][ee] * rn_s[bb];
    }
}

// ============================================================================
// launch
// ============================================================================
extern "C" void kernel_launch(void* const* d_in, const int* in_sizes, int n_in,
                              void* d_out, int out_size)
{
    const float *x, *Wp, *bp, *pos, *gamma, *beta, *Wh, *bh;
    const float *f0, *o0, *f1, *o1, *f2, *o2, *f3, *o3;

    x   = (const float*)d_in[0];
    Wp  = (const float*)d_in[1];
    bp  = (const float*)d_in[2];
    pos = (const float*)d_in[3];
    if (in_sizes[4] == BOND) {          // setup_inputs() dict order
        gamma = (const float*)d_in[4];  beta = (const float*)d_in[5];
        Wh    = (const float*)d_in[6];  bh   = (const float*)d_in[7];
        f0 = (const float*)d_in[8];   o0 = (const float*)d_in[9];
        f1 = (const float*)d_in[10];  o1 = (const float*)d_in[11];
        f2 = (const float*)d_in[12];  o2 = (const float*)d_in[13];
        f3 = (const float*)d_in[14];  o3 = (const float*)d_in[15];
    } else {                            // reference-signature order fallback
        f0 = (const float*)d_in[4];   o0 = (const float*)d_in[5];
        f1 = (const float*)d_in[6];   o1 = (const float*)d_in[7];
        f2 = (const float*)d_in[8];   o2 = (const float*)d_in[9];
        f3 = (const float*)d_in[10];  o3 = (const float*)d_in[11];
        gamma = (const float*)d_in[12]; beta = (const float*)d_in[13];
        Wh    = (const float*)d_in[14]; bh   = (const float*)d_in[15];
    }
    float* outp = (float*)d_out;

    const int SM_K1   = (64 * 132 + 64 * 128) * (int)sizeof(float);        // 66560
    const int SM_CP32 = (4 * 128 * 36 + 4 * 32 * 64) * (int)sizeof(float); // 106496
    const int SM_CP8  = (4 * 128 * 12 + 4 * 32 * 64) * (int)sizeof(float); // 57344
    const int SM_CP4  = (4 * 128 * 8  + 4 * 32 * 64) * (int)sizeof(float); // 49152

    cudaFuncSetAttribute((const void*)patch_embed_kernel,
                         cudaFuncAttributeMaxDynamicSharedMemorySize, SM_K1);
    cudaFuncSetAttribute((const void*)cp_level_v3<32>,
                         cudaFuncAttributeMaxDynamicSharedMemorySize, SM_CP32);
    cudaFuncSetAttribute((const void*)cp_level_v3<8>,
                         cudaFuncAttributeMaxDynamicSharedMemorySize, SM_CP8);
    cudaFuncSetAttribute((const void*)cp_level_v3<4>,
                         cudaFuncAttributeMaxDynamicSharedMemorySize, SM_CP4);

    float *h0, *h1, *h2, *h3, *h4;
    cudaGetSymbolAddress((void**)&h0, g_h0);
    cudaGetSymbolAddress((void**)&h1, g_h1);
    cudaGetSymbolAddress((void**)&h2, g_h2);
    cudaGetSymbolAddress((void**)&h3, g_h3);
    cudaGetSymbolAddress((void**)&h4, g_h4);

    patch_embed_kernel<<<1024, 256, SM_K1>>>(x, Wp, bp, pos);

    cp_level_v3<32><<<dim3(BATCH / 32, 64), 256, SM_CP32>>>(h0, h1, f0, o0, 16);
    cp_level_v3<32><<<dim3(BATCH / 32, 16), 256, SM_CP32>>>(h1, h2, f1, o1, 8);
    cp_level_v3<8> <<<dim3(BATCH / 8,  4),  256, SM_CP8 >>>(h2, h3, f2, o2, 4);
    cp_level_v3<4> <<<dim3(BATCH / 4,  1),  256, SM_CP4 >>>(h3, h4, f3, o3, 2);

    head_kernel<<<BATCH / 8, 512>>>(gamma, beta, Wh, bh, outp);
}